// round 8
// baseline (speedup 1.0000x reference)
#include <cuda_runtime.h>
#include <math.h>

// Output: spikes[t, b, n] = (t == spike_time[b,n]) ? 1.f : 0.f
// spike_time = floor(sigmoid(x) * (T-1)) with XLA-bit-exact f32 sigmoid:
//   s = 1 / (1 + __nv_expf(-x)), every op f32-rounded (verified rel_err==0).
//
// R8: two-phase. Phase 1 computes spike times ONCE into a 1MB __device__
// uint8 buffer (T=100 < 256). Phase 2 is a pure streaming kernel: one uchar4
// load (L2-resident) + 5 compare-built float4 __stcs per block, TSPLIT=20
// (20480 blocks) for fine wave granularity. No exp/div recompute bubbles.

extern "C" __device__ float __nv_expf(float);  // libdevice precise expf

__device__ __forceinline__ int xla_spike_time(float x, float tm1) {
    float e = __nv_expf(-x);                       // f32 exp(-x), libdevice
    float s = __fdiv_rn(1.0f, __fadd_rn(1.0f, e)); // 1/(1+e), f32 rn
    return (int)floorf(__fmul_rn(s, tm1));         // floor(s*(T-1))
}

// Static scratch: spike time per (b,n) element, 1 byte each.
#define SPIKE_CAP (1 << 20)
__device__ unsigned char g_spike_times[SPIKE_CAP];

// Phase 1: spike times -> uint8 buffer. One uchar4 store per thread.
__global__ void __launch_bounds__(256)
compute_spike_times(const float4* __restrict__ in, int BN4, float tm1)
{
    int idx = blockIdx.x * blockDim.x + threadIdx.x;
    if (idx >= BN4) return;
    float4 x = in[idx];
    uchar4 st;
    st.x = (unsigned char)xla_spike_time(x.x, tm1);
    st.y = (unsigned char)xla_spike_time(x.y, tm1);
    st.z = (unsigned char)xla_spike_time(x.z, tm1);
    st.w = (unsigned char)xla_spike_time(x.w, tm1);
    reinterpret_cast<uchar4*>(g_spike_times)[idx] = st;
}

// Phase 2: pure write stream. uchar4 load + TCHUNK coalesced STG.128.
template <int T, int TSPLIT>
__global__ void __launch_bounds__(256)
temporal_stream(float4* __restrict__ out, int BN4)
{
    int idx = blockIdx.x * blockDim.x + threadIdx.x;
    if (idx >= BN4) return;

    uchar4 stc = reinterpret_cast<const uchar4*>(g_spike_times)[idx];
    int st0 = stc.x, st1 = stc.y, st2 = stc.z, st3 = stc.w;

    constexpr int TCHUNK = T / TSPLIT;   // 5
    const int t0 = blockIdx.y * TCHUNK;

    const size_t stride4 = (size_t)BN4;  // float4 units == B*N floats
    float4* p = out + (size_t)t0 * stride4 + idx;
#pragma unroll
    for (int i = 0; i < TCHUNK; i++) {
        int t = t0 + i;
        float4 v;
        v.x = (st0 == t) ? 1.0f : 0.0f;
        v.y = (st1 == t) ? 1.0f : 0.0f;
        v.z = (st2 == t) ? 1.0f : 0.0f;
        v.w = (st3 == t) ? 1.0f : 0.0f;
        __stcs(p, v);          // streaming store, evict-first
        p += stride4;
    }
}

// Generic fallback: fused single kernel, dynamic T (no scratch dependence).
__global__ void __launch_bounds__(256)
temporal_encode_fused_dyn(const float4* __restrict__ in,
                          float4* __restrict__ out,
                          int BN4, int T)
{
    int idx = blockIdx.x * blockDim.x + threadIdx.x;
    if (idx >= BN4) return;

    float4 x = in[idx];
    const float tm1 = (float)(T - 1);
    int st0 = xla_spike_time(x.x, tm1);
    int st1 = xla_spike_time(x.y, tm1);
    int st2 = xla_spike_time(x.z, tm1);
    int st3 = xla_spike_time(x.w, tm1);

    float4* p = out + idx;
    const size_t stride4 = (size_t)BN4;
#pragma unroll 4
    for (int t = 0; t < T; t++) {
        float4 v;
        v.x = (st0 == t) ? 1.0f : 0.0f;
        v.y = (st1 == t) ? 1.0f : 0.0f;
        v.z = (st2 == t) ? 1.0f : 0.0f;
        v.w = (st3 == t) ? 1.0f : 0.0f;
        __stcs(p, v);
        p += stride4;
    }
}

extern "C" void kernel_launch(void* const* d_in, const int* in_sizes, int n_in,
                              void* d_out, int out_size)
{
    const float* in = (const float*)d_in[0];
    float4* out = (float4*)d_out;

    const int BN = in_sizes[0];   // B * N = 1048576
    const int T = out_size / BN;  // timesteps = 100
    const int BN4 = BN / 4;

    const int threads = 256;
    const int cblocks = (BN4 + threads - 1) / threads;

    if (T == 100 && BN <= SPIKE_CAP && (BN4 % threads) == 0) {
        compute_spike_times<<<cblocks, threads>>>(
            (const float4*)in, BN4, (float)(T - 1));
        dim3 grid(cblocks, 20);   // 1024 x 20 = 20480 blocks, 5 planes each
        temporal_stream<100, 20><<<grid, threads>>>(out, BN4);
    } else {
        temporal_encode_fused_dyn<<<cblocks, threads>>>(
            (const float4*)in, out, BN4, T);
    }
}

// round 9
// speedup vs baseline: 1.0381x; 1.0381x over previous
#include <cuda_runtime.h>
#include <math.h>

// Output: spikes[t, b, n] = (t == spike_time[b,n]) ? 1.f : 0.f
// spike_time = floor(sigmoid(x) * (T-1)) with XLA-bit-exact f32 sigmoid:
//   s = 1 / (1 + __nv_expf(-x)), every op f32-rounded (verified rel_err==0).
//
// R9: single fused kernel, TSPLIT=20 (20480 blocks, 5 planes each).
// R8 showed the split-phase precompute cost (~3us) exceeded its benefit;
// sigmoid recompute per block is nearly free. Fine TSPLIT keeps the wave
// granularity that gave the best kernel-only time (58.7us in R8).
// DRAM write stream is at ~78% of HBM spec = the observed ceiling.

extern "C" __device__ float __nv_expf(float);  // libdevice precise expf

__device__ __forceinline__ int xla_spike_time(float x, float tm1) {
    float e = __nv_expf(-x);                       // f32 exp(-x), libdevice
    float s = __fdiv_rn(1.0f, __fadd_rn(1.0f, e)); // 1/(1+e), f32 rn
    return (int)floorf(__fmul_rn(s, tm1));         // floor(s*(T-1))
}

template <int T, int TSPLIT>
__global__ void __launch_bounds__(256)
temporal_encode_fused(const float4* __restrict__ in,
                      float4* __restrict__ out,
                      int BN4)  // B*N/4
{
    int idx = blockIdx.x * blockDim.x + threadIdx.x;
    if (idx >= BN4) return;

    float4 x = __ldg(in + idx);   // L2-resident after first wave
    const float tm1 = (float)(T - 1);
    int st0 = xla_spike_time(x.x, tm1);
    int st1 = xla_spike_time(x.y, tm1);
    int st2 = xla_spike_time(x.z, tm1);
    int st3 = xla_spike_time(x.w, tm1);

    constexpr int TCHUNK = T / TSPLIT;   // 5
    const int t0 = blockIdx.y * TCHUNK;

    const size_t stride4 = (size_t)BN4;  // float4 units == B*N floats
    float4* p = out + (size_t)t0 * stride4 + idx;
#pragma unroll
    for (int i = 0; i < TCHUNK; i++) {
        int t = t0 + i;
        float4 v;
        v.x = (st0 == t) ? 1.0f : 0.0f;
        v.y = (st1 == t) ? 1.0f : 0.0f;
        v.z = (st2 == t) ? 1.0f : 0.0f;
        v.w = (st3 == t) ? 1.0f : 0.0f;
        __stcs(p, v);          // streaming store, evict-first
        p += stride4;
    }
}

// Generic-T fallback (single split, dynamic trip count)
__global__ void __launch_bounds__(256)
temporal_encode_fused_dyn(const float4* __restrict__ in,
                          float4* __restrict__ out,
                          int BN4, int T)
{
    int idx = blockIdx.x * blockDim.x + threadIdx.x;
    if (idx >= BN4) return;

    float4 x = in[idx];
    const float tm1 = (float)(T - 1);
    int st0 = xla_spike_time(x.x, tm1);
    int st1 = xla_spike_time(x.y, tm1);
    int st2 = xla_spike_time(x.z, tm1);
    int st3 = xla_spike_time(x.w, tm1);

    float4* p = out + idx;
    const size_t stride4 = (size_t)BN4;
#pragma unroll 4
    for (int t = 0; t < T; t++) {
        float4 v;
        v.x = (st0 == t) ? 1.0f : 0.0f;
        v.y = (st1 == t) ? 1.0f : 0.0f;
        v.z = (st2 == t) ? 1.0f : 0.0f;
        v.w = (st3 == t) ? 1.0f : 0.0f;
        __stcs(p, v);
        p += stride4;
    }
}

extern "C" void kernel_launch(void* const* d_in, const int* in_sizes, int n_in,
                              void* d_out, int out_size)
{
    const float* in = (const float*)d_in[0];
    float4* out = (float4*)d_out;

    const int BN = in_sizes[0];   // B * N = 1048576
    const int T = out_size / BN;  // timesteps = 100
    const int BN4 = BN / 4;

    const int threads = 256;
    const int cblocks = (BN4 + threads - 1) / threads;

    if (T == 100) {
        dim3 grid(cblocks, 20);   // 1024 x 20 = 20480 blocks, 5 planes each
        temporal_encode_fused<100, 20><<<grid, threads>>>(
            (const float4*)in, out, BN4);
    } else {
        temporal_encode_fused_dyn<<<cblocks, threads>>>(
            (const float4*)in, out, BN4, T);
    }
}